// round 8
// baseline (speedup 1.0000x reference)
#include <cuda_runtime.h>
#include <cuda_bf16.h>
#include <math.h>
#include <stdint.h>

#define BB 256
#define TT 256
#define DD 128
#define HH 512
#define G3 1536
#define NCTA 148
#define NTH 512
typedef unsigned u32;
typedef __nv_bfloat16 bf;

__device__ float g_h[BB*HH];
__device__ float g_hp[BB*HH];
__device__ float g_gh0[BB*G3];
__device__ bf g_h_hi[BB*HH],  g_h_lo[BB*HH];
__device__ bf g_hp_hi[BB*HH], g_hp_lo[BB*HH];
__device__ bf g_imp_hi[BB*DD], g_imp_lo[BB*DD];
__device__ unsigned g_bar;
__device__ bf wA_hi[1664*HH], wA_lo[1664*HH];  // [W_hh0 ; W_out]
__device__ bf wB_hi[G3*DD],   wB_lo[G3*DD];    // W_ih0 gate-blocked by 8
__device__ bf wC_hi[3072*HH], wC_lo[3072*HH];  // [i-gates(24) | h-gates(24)] per 8-j block

__device__ __forceinline__ void splitw(float x, bf* hi, bf* lo){
    bf h = __float2bfloat16(x);
    *hi = h; *lo = __float2bfloat16(x - __bfloat162float(h));
}

__global__ void init_kernel(const float* W_ih0, const float* W_hh0,
                            const float* W_ih1, const float* W_hh1,
                            const float* W_out){
    int idx = blockIdx.x*blockDim.x + threadIdx.x;
    int gs  = gridDim.x*blockDim.x;
    if (idx == 0) g_bar = 0u;
    for (int i = idx; i < BB*HH; i += gs){
        g_h[i] = 0.f; g_h_hi[i] = __float2bfloat16(0.f); g_h_lo[i] = __float2bfloat16(0.f);
    }
    for (int i = idx; i < 1664*HH; i += gs){
        int n = i/HH, k = i - n*HH;
        float x = (n < G3) ? W_hh0[(size_t)n*HH + k] : W_out[(size_t)(n-G3)*HH + k];
        splitw(x, &wA_hi[i], &wA_lo[i]);
    }
    for (int i = idx; i < G3*DD; i += gs){
        int q = i/DD, k = i - q*DD;
        int gi = q/24, w = q%24, gate = w>>3, j = gi*8 + (w&7);
        splitw(W_ih0[(size_t)(gate*HH + j)*DD + k], &wB_hi[i], &wB_lo[i]);
    }
    for (int i = idx; i < 3072*HH; i += gs){
        int q = i/HH, k = i - q*HH;
        int gi = q/48, w = q%48, half = w/24, g3 = (w%24)>>3, jo = w&7;
        int j = gi*8 + jo;
        float x = (half == 0) ? W_ih1[(size_t)(g3*HH + j)*HH + k]
                              : W_hh1[(size_t)(g3*HH + j)*HH + k];
        splitw(x, &wC_hi[i], &wC_lo[i]);
    }
}

__device__ __forceinline__ u32 s2u(const void* p){
    u32 a; asm("{ .reg .u64 t; cvta.to.shared.u64 t, %1; cvt.u32.u64 %0, t; }" : "=r"(a) : "l"(p));
    return a;
}
__device__ __forceinline__ void cpasync16(u32 dst, const void* src){
    asm volatile("cp.async.cg.shared.global [%0], [%1], 16;" :: "r"(dst), "l"(src));
}
#define CP_COMMIT() asm volatile("cp.async.commit_group;" ::: "memory")
#define CP_WAIT0()  asm volatile("cp.async.wait_group 0;" ::: "memory")

__device__ __forceinline__ void mma_bf(float* d, u32 a0,u32 a1,u32 a2,u32 a3, u32 b0,u32 b1){
    asm volatile("mma.sync.aligned.m16n8k16.row.col.f32.bf16.bf16.f32 "
        "{%0,%1,%2,%3},{%4,%5,%6,%7},{%8,%9},{%0,%1,%2,%3};"
        : "+f"(d[0]),"+f"(d[1]),"+f"(d[2]),"+f"(d[3])
        : "r"(a0),"r"(a1),"r"(a2),"r"(a3),"r"(b0),"r"(b1));
}

__device__ __forceinline__ void grid_barrier(unsigned &target){
    __syncthreads();
    target += gridDim.x;
    if (threadIdx.x == 0){
        __threadfence();
        atomicAdd(&g_bar, 1u);
        int sp = 0;
        while (*((volatile unsigned*)&g_bar) < target)
            if (++sp > 256) __nanosleep(32);
    }
    __syncthreads();
}
__device__ __forceinline__ float sigf(float x){ return 1.f/(1.f+expf(-x)); }

// smem map (bytes). rows: 144B (64 bf16 + pad)
#define WHA_OFF 0u              /* [8][32][144] = 36864 */
#define WHB_HI  36864u          /* [2][24][144] = 6912 */
#define WHB_LO  43776u
#define WHC_OFF 50688u          /* [8][48][144] = 55296 */
#define BUF0    105984u
#define BUF_SZ  43776u          /* AH 18432 | AL 18432 | WL 6912 */
#define AH_OFF  0u
#define AL_OFF  18432u
#define WL_OFF  36864u
#define XBUF    193536u         /* 12288 B exchange/reduce buffer */
#define SMEMSZ  (193536 + 12288)

extern __shared__ __align__(16) char smc[];

template<int NR, bool WRES>
__device__ __forceinline__ void load_chunk(int buf, const bf* Ahi, const bf* Alo, int lda,
                                           const bf* Wlo, int KW, int kc)
{
    const int tid = threadIdx.x;
    const u32 b = s2u(smc) + BUF0 + (u32)buf*BUF_SZ;
    #pragma unroll
    for (int i = 0; i < 2; i++){
        int seg = tid + i*NTH;             // 1024: 128 rows x 8
        int r = seg >> 3, c = seg & 7;
        u32 d = b + r*144 + c*16;
        cpasync16(d + AH_OFF, Ahi + (size_t)r*lda + kc + c*8);
        cpasync16(d + AL_OFF, Alo + (size_t)r*lda + kc + c*8);
    }
    if (!WRES){
        for (int seg = tid; seg < NR*8; seg += NTH){
            int r = seg >> 3, c = seg & 7;
            cpasync16(b + WL_OFF + r*144 + c*16, Wlo + (size_t)r*KW + kc + c*8);
        }
    }
}

// 16m x (8*NFR) warp tile; accH: hi*hi chain, accM: mixed chain (independent)
template<int NFR>
__device__ __forceinline__ void mma_chunk(const char* Abh, const char* Abl,
                                          const char* Wh, const char* Wl,
                                          int wm, int wn,
                                          float (*accH)[4], float (*accM)[4])
{
    const int lane = threadIdx.x & 31;
    const int g = lane >> 2, t = lane & 3;
    #pragma unroll
    for (int k16 = 0; k16 < 4; k16++){
        const int kb = k16*32 + 4*t;
        const char* r0 = Abh + (wm + g)*144 + kb;
        const char* r1 = r0 + 8*144;
        u32 ah0 = *(const u32*)r0,      ah1 = *(const u32*)r1;
        u32 ah2 = *(const u32*)(r0+16), ah3 = *(const u32*)(r1+16);
        const char* l0 = Abl + (wm + g)*144 + kb;
        const char* l1 = l0 + 8*144;
        u32 al0 = *(const u32*)l0,      al1 = *(const u32*)l1;
        u32 al2 = *(const u32*)(l0+16), al3 = *(const u32*)(l1+16);
        #pragma unroll
        for (int nf = 0; nf < NFR; nf++){
            const char* rh = Wh + (wn + 8*nf + g)*144 + kb;
            const char* rl = Wl + (wn + 8*nf + g)*144 + kb;
            u32 bh0 = *(const u32*)rh, bh1 = *(const u32*)(rh+16);
            u32 bl0 = *(const u32*)rl, bl1 = *(const u32*)(rl+16);
            mma_bf(accH[nf], ah0,ah1,ah2,ah3, bh0,bh1);
            mma_bf(accM[nf], ah0,ah1,ah2,ah3, bl0,bl1);
            mma_bf(accM[nf], al0,al1,al2,al3, bh0,bh1);
        }
    }
}

template<int NC, int NR, int NFR, bool WRES>
__device__ __forceinline__ void gemm_run(u32 whiOff, u32 wloResOff,
    const bf* Wlo, int KW, const bf* Ahi, const bf* Alo, int lda,
    int wm, int wn, float (*accH)[4], float (*accM)[4])
{
    #pragma unroll
    for (int n = 0; n < NFR; n++)
        #pragma unroll
        for (int q = 0; q < 4; q++){ accH[n][q] = 0.f; accM[n][q] = 0.f; }

    load_chunk<NR,WRES>(0, Ahi, Alo, lda, Wlo, KW, 0);
    CP_COMMIT();
    for (int ch = 0; ch < NC; ch++){
        CP_WAIT0();
        __syncthreads();
        if (ch + 1 < NC){
            load_chunk<NR,WRES>((ch+1)&1, Ahi, Alo, lda, Wlo, KW, (ch+1)*64);
            CP_COMMIT();
        }
        const char* bufc = smc + BUF0 + (ch&1)*BUF_SZ;
        mma_chunk<NFR>(bufc + AH_OFF, bufc + AL_OFF,
                       smc + whiOff + (u32)ch*NR*144,
                       WRES ? (smc + wloResOff + (u32)ch*NR*144) : (bufc + WL_OFF),
                       wm, wn, accH, accM);
        __syncthreads();
    }
}

__global__ void __launch_bounds__(NTH, 1) brits_kernel(
    const float* __restrict__ X,     const float* __restrict__ Msk,
    const float* __restrict__ b_ih0, const float* __restrict__ b_hh0,
    const float* __restrict__ b_ih1, const float* __restrict__ b_hh1,
    const float* __restrict__ W_out, const float* __restrict__ b_out,
    float* __restrict__ out)
{
    const int tid = threadIdx.x, wid = tid >> 5, lane = tid & 31, bx = blockIdx.x;
    const int g = lane >> 2, t = lane & 3;
    const int wg = wid >> 3;                 // warp-group 0/1
    const int wm = (wid & 7) * 16;           // m offset within 128-row tile
    float* xbuf = (float*)(smc + XBUF);

    // ---- preload resident weights ----
    {
        const int nA = (bx >> 1) * 32;
        const int qB = (bx >> 1) * 24;
        const int qC = (bx >> 1) * 48;
        if (bx < 104)
            for (int s = tid; s < 8*32*8; s += NTH){
                int ch = s >> 8, r = (s >> 3) & 31, c = s & 7;
                *(uint4*)(smc + WHA_OFF + (ch*32 + r)*144 + c*16) =
                    __ldg((const uint4*)(wA_hi + (size_t)(nA + r)*HH + ch*64 + c*8));
            }
        if (bx < 128){
            for (int s = tid; s < 2*24*8; s += NTH){
                int ch = s / 192, r = (s >> 3) % 24, c = s & 7;
                *(uint4*)(smc + WHB_HI + (ch*24 + r)*144 + c*16) =
                    __ldg((const uint4*)(wB_hi + (size_t)(qB + r)*DD + ch*64 + c*8));
                *(uint4*)(smc + WHB_LO + (ch*24 + r)*144 + c*16) =
                    __ldg((const uint4*)(wB_lo + (size_t)(qB + r)*DD + ch*64 + c*8));
            }
            for (int s = tid; s < 8*48*8; s += NTH){
                int ch = s / 384, r = (s >> 3) % 48, c = s & 7;
                *(uint4*)(smc + WHC_OFF + (ch*48 + r)*144 + c*16) =
                    __ldg((const uint4*)(wC_hi + (size_t)(qC + r)*HH + ch*64 + c*8));
            }
        }
        __syncthreads();
    }

    float* pre_o = out;
    float* out_o = out + (size_t)BB*TT*DD;
    float* hf_o  = out + (size_t)2*BB*TT*DD;
    float* hid_o = hf_o + (size_t)BB*HH;

    unsigned target = 0;
    const int gs   = gridDim.x * blockDim.x;
    const int gtid = bx * blockDim.x + tid;

    for (int ts = 0; ts < TT; ts++){
        // ---- A: [gh0 | est]. 104 CTAs, 128m x 32n; warp groups split n.
        if (bx < 104){
            const int m0 = (bx & 1) * 128, n0 = (bx >> 1) * 32;
            const int wn = wg * 16;
            float accH[2][4], accM[2][4];
            gemm_run<8,32,2,false>(WHA_OFF, 0u, wA_lo + (size_t)n0*HH, HH,
                g_h_hi + (size_t)m0*HH, g_h_lo + (size_t)m0*HH, HH, wm, wn, accH, accM);
            #pragma unroll
            for (int nf = 0; nf < 2; nf++)
                #pragma unroll
                for (int rh = 0; rh < 2; rh++)
                    #pragma unroll
                    for (int d = 0; d < 2; d++){
                        int m = m0 + wm + g + 8*rh;
                        int n = n0 + wn + 8*nf + 2*t + d;
                        float v = accH[nf][rh*2+d] + accM[nf][rh*2+d];
                        if (n < G3) g_gh0[m*G3 + n] = v + b_hh0[n];
                        else {
                            int dd = n - G3;
                            float est = v + b_out[dd];
                            int io = (m*TT + ts)*DD + dd;
                            pre_o[io] = est;
                            float imp = est + Msk[io] * (X[io] - est);
                            bf hi = __float2bfloat16(imp);
                            g_imp_hi[m*DD + dd] = hi;
                            g_imp_lo[m*DD + dd] = __float2bfloat16(imp - __bfloat162float(hi));
                            if (ts > 0) out_o[io - DD] = imp;
                        }
                    }
        }
        grid_barrier(target);

        // ---- B: fused cell-0. 128 CTAs, 128m x 24n, K=128 split-K across warp groups.
        if (bx < 128){
            const int m0 = (bx & 1) * 128, j0 = (bx >> 1) * 8;
            float accH[3][4], accM[3][4];
            #pragma unroll
            for (int n = 0; n < 3; n++)
                #pragma unroll
                for (int q = 0; q < 4; q++){ accH[n][q] = 0.f; accM[n][q] = 0.f; }
            load_chunk<24,true>(0, g_imp_hi + (size_t)m0*DD, g_imp_lo + (size_t)m0*DD, DD, (const bf*)0, DD, 0);
            load_chunk<24,true>(1, g_imp_hi + (size_t)m0*DD, g_imp_lo + (size_t)m0*DD, DD, (const bf*)0, DD, 64);
            CP_COMMIT(); CP_WAIT0();
            __syncthreads();
            const char* bufc = smc + BUF0 + wg*BUF_SZ;
            mma_chunk<3>(bufc + AH_OFF, bufc + AL_OFF,
                         smc + WHB_HI + (u32)wg*24*144, smc + WHB_LO + (u32)wg*24*144,
                         wm, 0, accH, accM);
            if (wg == 1)
                #pragma unroll
                for (int nf = 0; nf < 3; nf++)
                    #pragma unroll
                    for (int rh = 0; rh < 2; rh++)
                        #pragma unroll
                        for (int d = 0; d < 2; d++)
                            xbuf[(wm + g + 8*rh)*24 + nf*8 + 2*t + d] =
                                accH[nf][rh*2+d] + accM[nf][rh*2+d];
            __syncthreads();
            if (wg == 0)
                #pragma unroll
                for (int rh = 0; rh < 2; rh++)
                    #pragma unroll
                    for (int d = 0; d < 2; d++){
                        int m = m0 + wm + g + 8*rh;
                        int j = j0 + 2*t + d;
                        int q = rh*2 + d;
                        int xb = (wm + g + 8*rh)*24 + 2*t + d;
                        float gr = accH[0][q]+accM[0][q] + xbuf[xb]      + b_ih0[j]      + __ldcg(&g_gh0[m*G3 + j]);
                        float gz = accH[1][q]+accM[1][q] + xbuf[xb+8]    + b_ih0[HH + j] + __ldcg(&g_gh0[m*G3 + HH + j]);
                        float gn = accH[2][q]+accM[2][q] + xbuf[xb+16]   + b_ih0[2*HH + j];
                        float hn = __ldcg(&g_gh0[m*G3 + 2*HH + j]);
                        float r = sigf(gr), z = sigf(gz);
                        float nn = tanhf(gn + r * hn);
                        float hp = (1.f - z) * nn + z * __ldcg(&g_h[m*HH + j]);
                        g_hp[m*HH + j] = hp;
                        bf hi = __float2bfloat16(hp);
                        g_hp_hi[m*HH + j] = hi;
                        g_hp_lo[m*HH + j] = __float2bfloat16(hp - __bfloat162float(hi));
                    }
        }
        grid_barrier(target);

        // ---- C: fused cell-1. 128 CTAs, 128m x 48n (wg0: i-gates, wg1: h-gates), K=512
        if (bx < 128){
            const int m0 = (bx & 1) * 128, q0 = (bx >> 1) * 48, j0 = (bx >> 1) * 8;
            const int wn = wg * 24;
            float accH[3][4], accM[3][4];
            gemm_run<8,48,3,false>(WHC_OFF, 0u, wC_lo + (size_t)q0*HH, HH,
                g_hp_hi + (size_t)m0*HH, g_hp_lo + (size_t)m0*HH, HH, wm, wn, accH, accM);
            if (wg == 1)
                #pragma unroll
                for (int nf = 0; nf < 3; nf++)
                    #pragma unroll
                    for (int rh = 0; rh < 2; rh++)
                        #pragma unroll
                        for (int d = 0; d < 2; d++)
                            xbuf[((wm + g + 8*rh)*8 + 2*t + d)*3 + nf] =
                                accH[nf][rh*2+d] + accM[nf][rh*2+d];
            __syncthreads();
            if (wg == 0)
                #pragma unroll
                for (int rh = 0; rh < 2; rh++)
                    #pragma unroll
                    for (int d = 0; d < 2; d++){
                        int ml = wm + g + 8*rh, m = m0 + ml;
                        int jo = 2*t + d, j = j0 + jo;
                        int q = rh*2 + d;
                        const float* xb = &xbuf[(ml*8 + jo)*3];
                        float ir = accH[0][q]+accM[0][q], iz = accH[1][q]+accM[1][q], in_ = accH[2][q]+accM[2][q];
                        float hr = xb[0], hz = xb[1], hn = xb[2];
                        float r = sigf(ir + b_ih1[j] + hr + b_hh1[j]);
                        float z = sigf(iz + b_ih1[HH+j] + hz + b_hh1[HH+j]);
                        float nn = tanhf(in_ + b_ih1[2*HH+j] + r * (hn + b_hh1[2*HH+j]));
                        float hnew = (1.f - z) * nn + z * __ldcg(&g_hp[m*HH + j]);
                        g_h[m*HH + j] = hnew;
                        bf hi = __float2bfloat16(hnew);
                        g_h_hi[m*HH + j] = hi;
                        g_h_lo[m*HH + j] = __float2bfloat16(hnew - __bfloat162float(hi));
                        hid_o[((size_t)m*TT + ts)*HH + j] = hnew;
                    }
        }
        grid_barrier(target);
    }

    // tail
    for (int idx = gtid; idx < BB*DD; idx += gs){
        int b = idx >> 7, d = idx & 127;
        const float4* hv = (const float4*)(g_h + (size_t)b*HH);
        const float4* wv = (const float4*)(W_out + (size_t)d*HH);
        float s = b_out[d];
        #pragma unroll 8
        for (int q = 0; q < HH/4; q++){
            float4 a = __ldcg(&hv[q]); float4 w = __ldg(&wv[q]);
            s += a.x*w.x + a.y*w.y + a.z*w.z + a.w*w.w;
        }
        out_o[((size_t)b*TT + (TT-1))*DD + d] = s;
    }
    for (int idx = gtid; idx < BB*HH; idx += gs)
        hf_o[idx] = __ldcg(&g_h[idx]);
}

extern "C" void kernel_launch(void* const* d_in, const int* in_sizes, int n_in,
                              void* d_out, int out_size) {
    const float* X     = (const float*)d_in[0];
    const float* Msk   = (const float*)d_in[1];
    const float* W_ih0 = (const float*)d_in[2];
    const float* W_hh0 = (const float*)d_in[3];
    const float* b_ih0 = (const float*)d_in[4];
    const float* b_hh0 = (const float*)d_in[5];
    const float* W_ih1 = (const float*)d_in[6];
    const float* W_hh1 = (const float*)d_in[7];
    const float* b_ih1 = (const float*)d_in[8];
    const float* b_hh1 = (const float*)d_in[9];
    const float* W_out = (const float*)d_in[10];
    const float* b_out = (const float*)d_in[11];

    static bool attr_set = false;
    if (!attr_set){
        cudaFuncSetAttribute(brits_kernel, cudaFuncAttributeMaxDynamicSharedMemorySize, SMEMSZ);
        attr_set = true;
    }
    init_kernel<<<512, 256>>>(W_ih0, W_hh0, W_ih1, W_hh1, W_out);
    brits_kernel<<<NCTA, NTH, SMEMSZ>>>(X, Msk, b_ih0, b_hh0, b_ih1, b_hh1,
                                        W_out, b_out, (float*)d_out);
}

// round 9
// speedup vs baseline: 1.0498x; 1.0498x over previous
#include <cuda_runtime.h>
#include <cuda_bf16.h>
#include <math.h>
#include <stdint.h>

#define BB 256
#define TT 256
#define DD 128
#define HH 512
#define G3 1536
#define NCTA 148
#define NTH 512
typedef unsigned u32;
typedef __nv_bfloat16 bf;

__device__ float g_h[BB*HH];
__device__ float g_hp[BB*HH];
__device__ float g_gh0[BB*G3];
__device__ bf g_h_hi[BB*HH],  g_h_lo[BB*HH];
__device__ bf g_hp_hi[BB*HH], g_hp_lo[BB*HH];
__device__ bf g_imp_hi[BB*DD], g_imp_lo[BB*DD];
__device__ unsigned g_bar;
__device__ bf wA_hi[1664*HH], wA_lo[1664*HH];  // [W_hh0 ; W_out]
__device__ bf wB_hi[G3*DD],   wB_lo[G3*DD];    // W_ih0 gate-blocked by 8
__device__ bf wC_hi[3072*HH], wC_lo[3072*HH];  // [i-gates(24) | h-gates(24)] per 8-j block

__device__ __forceinline__ void splitw(float x, bf* hi, bf* lo){
    bf h = __float2bfloat16(x);
    *hi = h; *lo = __float2bfloat16(x - __bfloat162float(h));
}

__global__ void init_kernel(const float* W_ih0, const float* W_hh0,
                            const float* W_ih1, const float* W_hh1,
                            const float* W_out){
    int idx = blockIdx.x*blockDim.x + threadIdx.x;
    int gs  = gridDim.x*blockDim.x;
    if (idx == 0) g_bar = 0u;
    for (int i = idx; i < BB*HH; i += gs){
        g_h[i] = 0.f; g_h_hi[i] = __float2bfloat16(0.f); g_h_lo[i] = __float2bfloat16(0.f);
    }
    for (int i = idx; i < 1664*HH; i += gs){
        int n = i/HH, k = i - n*HH;
        float x = (n < G3) ? W_hh0[(size_t)n*HH + k] : W_out[(size_t)(n-G3)*HH + k];
        splitw(x, &wA_hi[i], &wA_lo[i]);
    }
    for (int i = idx; i < G3*DD; i += gs){
        int q = i/DD, k = i - q*DD;
        int gi = q/24, w = q%24, gate = w>>3, j = gi*8 + (w&7);
        splitw(W_ih0[(size_t)(gate*HH + j)*DD + k], &wB_hi[i], &wB_lo[i]);
    }
    for (int i = idx; i < 3072*HH; i += gs){
        int q = i/HH, k = i - q*HH;
        int gi = q/48, w = q%48, half = w/24, g3 = (w%24)>>3, jo = w&7;
        int j = gi*8 + jo;
        float x = (half == 0) ? W_ih1[(size_t)(g3*HH + j)*HH + k]
                              : W_hh1[(size_t)(g3*HH + j)*HH + k];
        splitw(x, &wC_hi[i], &wC_lo[i]);
    }
}

__device__ __forceinline__ u32 s2u(const void* p){
    u32 a; asm("{ .reg .u64 t; cvta.to.shared.u64 t, %1; cvt.u32.u64 %0, t; }" : "=r"(a) : "l"(p));
    return a;
}
__device__ __forceinline__ void cpasync16(u32 dst, const void* src){
    asm volatile("cp.async.cg.shared.global [%0], [%1], 16;" :: "r"(dst), "l"(src));
}
#define CP_COMMIT() asm volatile("cp.async.commit_group;" ::: "memory")
#define CP_WAIT0()  asm volatile("cp.async.wait_group 0;" ::: "memory")
#define CP_WAIT1()  asm volatile("cp.async.wait_group 1;" ::: "memory")
#define CP_WAIT2()  asm volatile("cp.async.wait_group 2;" ::: "memory")

__device__ __forceinline__ void mma_bf(float* d, u32 a0,u32 a1,u32 a2,u32 a3, u32 b0,u32 b1){
    asm volatile("mma.sync.aligned.m16n8k16.row.col.f32.bf16.bf16.f32 "
        "{%0,%1,%2,%3},{%4,%5,%6,%7},{%8,%9},{%0,%1,%2,%3};"
        : "+f"(d[0]),"+f"(d[1]),"+f"(d[2]),"+f"(d[3])
        : "r"(a0),"r"(a1),"r"(a2),"r"(a3),"r"(b0),"r"(b1));
}
__device__ __forceinline__ void ldsm4(u32* r, u32 a){
    asm volatile("ldmatrix.sync.aligned.m8n8.x4.shared.b16 {%0,%1,%2,%3}, [%4];"
        : "=r"(r[0]),"=r"(r[1]),"=r"(r[2]),"=r"(r[3]) : "r"(a));
}
__device__ __forceinline__ void ldsm2(u32* r, u32 a){
    asm volatile("ldmatrix.sync.aligned.m8n8.x2.shared.b16 {%0,%1}, [%2];"
        : "=r"(r[0]),"=r"(r[1]) : "r"(a));
}

__device__ __forceinline__ void grid_barrier(unsigned &target){
    __syncthreads();
    target += gridDim.x;
    if (threadIdx.x == 0){
        __threadfence();
        atomicAdd(&g_bar, 1u);
        int sp = 0;
        while (*((volatile unsigned*)&g_bar) < target)
            if (++sp > 256) __nanosleep(32);
    }
    __syncthreads();
}
__device__ __forceinline__ float sigf(float x){ return 1.f/(1.f+expf(-x)); }

// ---- smem: 4-buffer ring + resident phase-B weights. rows 144B stride.
#define AH_OFF  0u
#define AL_OFF  18432u
#define W1_OFF  36864u
#define W2_OFF  43776u
#define BUF_SZ  50688u
#define RESB_HI 202752u
#define RESB_LO 209664u
#define SMEMSZ  216576

extern __shared__ __align__(16) char smc[];

template<int WROWS>
__device__ __forceinline__ void load_chunk(int buf, const bf* Ahi, const bf* Alo, int lda,
                                           const bf* W1, const bf* W2, int KW, int kc)
{
    const int tid = threadIdx.x;
    const u32 b = s2u(smc) + (u32)buf*BUF_SZ;
    int seg = tid;
    #pragma unroll
    for (int i = 0; i < 2; i++, seg += NTH){
        int r = seg >> 3, c = seg & 7;
        u32 d = b + r*144 + c*16;
        cpasync16(d + AH_OFF, Ahi + (size_t)r*lda + kc + c*8);
        cpasync16(d + AL_OFF, Alo + (size_t)r*lda + kc + c*8);
    }
    if (WROWS > 0){
        for (int s = tid; s < WROWS*8; s += NTH){
            int r = s >> 3, c = s & 7;
            u32 d = b + r*144 + c*16;
            cpasync16(d + W1_OFF, W1 + (size_t)r*KW + kc + c*8);
            cpasync16(d + W2_OFF, W2 + (size_t)r*KW + kc + c*8);
        }
    }
}

template<int NFR>
__device__ __forceinline__ void mma_chunk(u32 sAh, u32 sAl, u32 sWh, u32 sWl,
                                          int wm, int wn, float (*accH)[4], float (*accM)[4])
{
    const int lane = threadIdx.x & 31;
    const int lg = lane & 7, grp = lane >> 3;
    const u32 arow = (u32)(wm + lg + (grp & 1)*8) * 144 + ((grp >> 1) & 1)*16;
    const int l16 = lane & 15;
    const u32 brow0 = (u32)(l16 & 7) * 144 + (u32)(l16 >> 3) * 16;
    #pragma unroll
    for (int k16 = 0; k16 < 4; k16++){
        u32 ah[4], al[4];
        ldsm4(ah, sAh + arow + k16*32);
        ldsm4(al, sAl + arow + k16*32);
        #pragma unroll
        for (int nf = 0; nf < NFR; nf++){
            u32 boff = brow0 + (u32)(wn + 8*nf)*144 + k16*32;
            u32 bh[2], bl[2];
            ldsm2(bh, sWh + boff);
            ldsm2(bl, sWl + boff);
            mma_bf(accH[nf], ah[0],ah[1],ah[2],ah[3], bh[0],bh[1]);
            mma_bf(accM[nf], ah[0],ah[1],ah[2],ah[3], bl[0],bl[1]);
            mma_bf(accM[nf], al[0],al[1],al[2],al[3], bh[0],bh[1]);
        }
    }
}

// 4-buffer ring, prefetch depth 2, ONE sync per chunk.
template<int NC, int WROWS, int NFR>
__device__ __forceinline__ void gemm_run(const bf* Ahi, const bf* Alo, int lda,
    const bf* W1, const bf* W2, int KW, int wm, int wn,
    float (*accH)[4], float (*accM)[4])
{
    #pragma unroll
    for (int n = 0; n < NFR; n++)
        #pragma unroll
        for (int q = 0; q < 4; q++){ accH[n][q] = 0.f; accM[n][q] = 0.f; }

    load_chunk<WROWS>(0, Ahi, Alo, lda, W1, W2, KW, 0);
    CP_COMMIT();
    if (NC > 1){
        load_chunk<WROWS>(1, Ahi, Alo, lda, W1, W2, KW, 64);
        CP_COMMIT();
    }
    const u32 sb = s2u(smc);
    for (int ch = 0; ch < NC; ch++){
        if (ch + 2 < NC){
            load_chunk<WROWS>((ch+2)&3, Ahi, Alo, lda, W1, W2, KW, (ch+2)*64);
            CP_COMMIT(); CP_WAIT2();
        } else if (ch + 1 < NC) CP_WAIT1();
        else CP_WAIT0();
        __syncthreads();
        const u32 b = sb + (u32)(ch&3)*BUF_SZ;
        mma_chunk<NFR>(b+AH_OFF, b+AL_OFF, b+W1_OFF, b+W2_OFF, wm, wn, accH, accM);
    }
}

__global__ void __launch_bounds__(NTH, 1) brits_kernel(
    const float* __restrict__ X,     const float* __restrict__ Msk,
    const float* __restrict__ b_ih0, const float* __restrict__ b_hh0,
    const float* __restrict__ b_ih1, const float* __restrict__ b_hh1,
    const float* __restrict__ W_out, const float* __restrict__ b_out,
    float* __restrict__ out)
{
    const int tid = threadIdx.x, wid = tid >> 5, lane = tid & 31, bx = blockIdx.x;
    const int g = lane >> 2, t = lane & 3;
    const int wg = wid >> 3;
    const int wm = (wid & 7) * 16;
    float* xbuf = (float*)(smc + 2*BUF_SZ);   // aliases buf2 (dead at epilogue time)

    // preload resident phase-B weights
    if (bx < 128){
        const int qB = (bx >> 1) * 24;
        for (int s = tid; s < 2*24*8; s += NTH){
            int ch = s / 192, r = (s >> 3) % 24, c = s & 7;
            *(uint4*)(smc + RESB_HI + (ch*24 + r)*144 + c*16) =
                __ldg((const uint4*)(wB_hi + (size_t)(qB + r)*DD + ch*64 + c*8));
            *(uint4*)(smc + RESB_LO + (ch*24 + r)*144 + c*16) =
                __ldg((const uint4*)(wB_lo + (size_t)(qB + r)*DD + ch*64 + c*8));
        }
    }
    __syncthreads();

    float* pre_o = out;
    float* out_o = out + (size_t)BB*TT*DD;
    float* hf_o  = out + (size_t)2*BB*TT*DD;
    float* hid_o = hf_o + (size_t)BB*HH;

    unsigned target = 0;
    const int gs   = gridDim.x * blockDim.x;
    const int gtid = bx * blockDim.x + tid;

    for (int ts = 0; ts < TT; ts++){
        // ---- A: [gh0 | est]. 104 CTAs, 128m x 32n (wg splits n). K=512
        if (bx < 104){
            const int m0 = (bx & 1) * 128, n0 = (bx >> 1) * 32;
            const int wn = wg * 16;
            float accH[2][4], accM[2][4];
            gemm_run<8,32,2>(g_h_hi + (size_t)m0*HH, g_h_lo + (size_t)m0*HH, HH,
                             wA_hi + (size_t)n0*HH, wA_lo + (size_t)n0*HH, HH, wm, wn, accH, accM);
            #pragma unroll
            for (int nf = 0; nf < 2; nf++)
                #pragma unroll
                for (int rh = 0; rh < 2; rh++)
                    #pragma unroll
                    for (int d = 0; d < 2; d++){
                        int m = m0 + wm + g + 8*rh;
                        int n = n0 + wn + 8*nf + 2*t + d;
                        float v = accH[nf][rh*2+d] + accM[nf][rh*2+d];
                        if (n < G3) g_gh0[m*G3 + n] = v + b_hh0[n];
                        else {
                            int dd = n - G3;
                            float est = v + b_out[dd];
                            int io = (m*TT + ts)*DD + dd;
                            pre_o[io] = est;
                            float imp = est + Msk[io] * (X[io] - est);
                            bf hi = __float2bfloat16(imp);
                            g_imp_hi[m*DD + dd] = hi;
                            g_imp_lo[m*DD + dd] = __float2bfloat16(imp - __bfloat162float(hi));
                            if (ts > 0) out_o[io - DD] = imp;
                        }
                    }
        }
        grid_barrier(target);

        // ---- B: fused cell-0. 128 CTAs, 128m x 24n, K=128 split across wg.
        if (bx < 128){
            const int m0 = (bx & 1) * 128, j0 = (bx >> 1) * 8;
            float accH[3][4], accM[3][4];
            #pragma unroll
            for (int n = 0; n < 3; n++)
                #pragma unroll
                for (int q = 0; q < 4; q++){ accH[n][q] = 0.f; accM[n][q] = 0.f; }
            load_chunk<0>(0, g_imp_hi + (size_t)m0*DD, g_imp_lo + (size_t)m0*DD, DD,
                          (const bf*)0, (const bf*)0, DD, 0);
            load_chunk<0>(1, g_imp_hi + (size_t)m0*DD, g_imp_lo + (size_t)m0*DD, DD,
                          (const bf*)0, (const bf*)0, DD, 64);
            CP_COMMIT(); CP_WAIT0();
            __syncthreads();
            const u32 sb = s2u(smc);
            const u32 b = sb + (u32)wg*BUF_SZ;
            mma_chunk<3>(b+AH_OFF, b+AL_OFF,
                         sb + RESB_HI + (u32)wg*24*144, sb + RESB_LO + (u32)wg*24*144,
                         wm, 0, accH, accM);
            __syncthreads();
            if (wg == 1)
                #pragma unroll
                for (int nf = 0; nf < 3; nf++)
                    #pragma unroll
                    for (int rh = 0; rh < 2; rh++)
                        #pragma unroll
                        for (int d = 0; d < 2; d++)
                            xbuf[(wm + g + 8*rh)*24 + nf*8 + 2*t + d] =
                                accH[nf][rh*2+d] + accM[nf][rh*2+d];
            __syncthreads();
            if (wg == 0)
                #pragma unroll
                for (int rh = 0; rh < 2; rh++)
                    #pragma unroll
                    for (int d = 0; d < 2; d++){
                        int m = m0 + wm + g + 8*rh;
                        int j = j0 + 2*t + d;
                        int q = rh*2 + d;
                        int xb = (wm + g + 8*rh)*24 + 2*t + d;
                        float gr = accH[0][q]+accM[0][q] + xbuf[xb]    + b_ih0[j]      + __ldcg(&g_gh0[m*G3 + j]);
                        float gz = accH[1][q]+accM[1][q] + xbuf[xb+8]  + b_ih0[HH + j] + __ldcg(&g_gh0[m*G3 + HH + j]);
                        float gn = accH[2][q]+accM[2][q] + xbuf[xb+16] + b_ih0[2*HH + j];
                        float hn = __ldcg(&g_gh0[m*G3 + 2*HH + j]);
                        float r = sigf(gr), z = sigf(gz);
                        float nn = tanhf(gn + r * hn);
                        float hp = (1.f - z) * nn + z * __ldcg(&g_h[m*HH + j]);
                        g_hp[m*HH + j] = hp;
                        bf hi = __float2bfloat16(hp);
                        g_hp_hi[m*HH + j] = hi;
                        g_hp_lo[m*HH + j] = __float2bfloat16(hp - __bfloat162float(hi));
                    }
        }
        grid_barrier(target);

        // ---- C: fused cell-1. 128 CTAs, 128m x 48n (wg0 i-gates, wg1 h-gates). K=512
        if (bx < 128){
            const int m0 = (bx & 1) * 128, q0 = (bx >> 1) * 48, j0 = (bx >> 1) * 8;
            const int wn = wg * 24;
            float accH[3][4], accM[3][4];
            gemm_run<8,48,3>(g_hp_hi + (size_t)m0*HH, g_hp_lo + (size_t)m0*HH, HH,
                             wC_hi + (size_t)q0*HH, wC_lo + (size_t)q0*HH, HH, wm, wn, accH, accM);
            if (wg == 1)
                #pragma unroll
                for (int nf = 0; nf < 3; nf++)
                    #pragma unroll
                    for (int rh = 0; rh < 2; rh++)
                        #pragma unroll
                        for (int d = 0; d < 2; d++)
                            xbuf[((wm + g + 8*rh)*8 + 2*t + d)*3 + nf] =
                                accH[nf][rh*2+d] + accM[nf][rh*2+d];
            __syncthreads();
            if (wg == 0)
                #pragma unroll
                for (int rh = 0; rh < 2; rh++)
                    #pragma unroll
                    for (int d = 0; d < 2; d++){
                        int ml = wm + g + 8*rh, m = m0 + ml;
                        int jo = 2*t + d, j = j0 + jo;
                        int q = rh*2 + d;
                        const float* xb = &xbuf[(ml*8 + jo)*3];
                        float ir = accH[0][q]+accM[0][q], iz = accH[1][q]+accM[1][q], in_ = accH[2][q]+accM[2][q];
                        float hr = xb[0], hz = xb[1], hn = xb[2];
                        float r = sigf(ir + b_ih1[j] + hr + b_hh1[j]);
                        float z = sigf(iz + b_ih1[HH+j] + hz + b_hh1[HH+j]);
                        float nn = tanhf(in_ + b_ih1[2*HH+j] + r * (hn + b_hh1[2*HH+j]));
                        float hnew = (1.f - z) * nn + z * __ldcg(&g_hp[m*HH + j]);
                        g_h[m*HH + j] = hnew;
                        bf hi = __float2bfloat16(hnew);
                        g_h_hi[m*HH + j] = hi;
                        g_h_lo[m*HH + j] = __float2bfloat16(hnew - __bfloat162float(hi));
                        hid_o[((size_t)m*TT + ts)*HH + j] = hnew;
                    }
        }
        grid_barrier(target);
    }

    // tail
    for (int idx = gtid; idx < BB*DD; idx += gs){
        int b = idx >> 7, d = idx & 127;
        const float4* hv = (const float4*)(g_h + (size_t)b*HH);
        const float4* wv = (const float4*)(W_out + (size_t)d*HH);
        float s = b_out[d];
        #pragma unroll 8
        for (int q = 0; q < HH/4; q++){
            float4 a = __ldcg(&hv[q]); float4 w = __ldg(&wv[q]);
            s += a.x*w.x + a.y*w.y + a.z*w.z + a.w*w.w;
        }
        out_o[((size_t)b*TT + (TT-1))*DD + d] = s;
    }
    for (int idx = gtid; idx < BB*HH; idx += gs)
        hf_o[idx] = __ldcg(&g_h[idx]);
}

extern "C" void kernel_launch(void* const* d_in, const int* in_sizes, int n_in,
                              void* d_out, int out_size) {
    const float* X     = (const float*)d_in[0];
    const float* Msk   = (const float*)d_in[1];
    const float* W_ih0 = (const float*)d_in[2];
    const float* W_hh0 = (const float*)d_in[3];
    const float* b_ih0 = (const float*)d_in[4];
    const float* b_hh0 = (const float*)d_in[5];
    const float* W_ih1 = (const float*)d_in[6];
    const float* W_hh1 = (const float*)d_in[7];
    const float* b_ih1 = (const float*)d_in[8];
    const float* b_hh1 = (const float*)d_in[9];
    const float* W_out = (const float*)d_in[10];
    const float* b_out = (const float*)d_in[11];

    static bool attr_set = false;
    if (!attr_set){
        cudaFuncSetAttribute(brits_kernel, cudaFuncAttributeMaxDynamicSharedMemorySize, SMEMSZ);
        attr_set = true;
    }
    init_kernel<<<512, 256>>>(W_ih0, W_hh0, W_ih1, W_hh1, W_out);
    brits_kernel<<<NCTA, NTH, SMEMSZ>>>(X, Msk, b_ih0, b_hh0, b_ih1, b_hh1,
                                        W_out, b_out, (float*)d_out);
}

// round 10
// speedup vs baseline: 1.0636x; 1.0131x over previous
#include <cuda_runtime.h>
#include <cuda_bf16.h>
#include <math.h>
#include <stdint.h>

#define BB 256
#define TT 256
#define DD 128
#define HH 512
#define G3 1536
#define NTH 256
typedef unsigned u32;
typedef __nv_bfloat16 bf;

__device__ float g_h[BB*HH];
__device__ float g_hp[BB*HH];
__device__ float g_gh0[BB*G3];
__device__ bf g_h_hi[BB*HH],  g_h_lo[BB*HH];
__device__ bf g_hp_hi[BB*HH], g_hp_lo[BB*HH];
__device__ bf g_imp_hi[BB*DD], g_imp_lo[BB*DD];
__device__ unsigned g_bar;
__device__ bf wA_hi[1664*HH], wA_lo[1664*HH];  // [W_hh0 ; W_out]
__device__ bf wB_hi[G3*DD],   wB_lo[G3*DD];    // W_ih0 gate-blocked by 8
__device__ bf wC_hi[3072*HH], wC_lo[3072*HH];  // [i-gates(24)|h-gates(24)] per 8-j block

__device__ __forceinline__ void splitw(float x, bf* hi, bf* lo){
    bf h = __float2bfloat16(x);
    *hi = h; *lo = __float2bfloat16(x - __bfloat162float(h));
}

__global__ void init_kernel(const float* W_ih0, const float* W_hh0,
                            const float* W_ih1, const float* W_hh1,
                            const float* W_out){
    int idx = blockIdx.x*blockDim.x + threadIdx.x;
    int gs  = gridDim.x*blockDim.x;
    if (idx == 0) g_bar = 0u;
    for (int i = idx; i < BB*HH; i += gs){
        g_h[i] = 0.f; g_h_hi[i] = __float2bfloat16(0.f); g_h_lo[i] = __float2bfloat16(0.f);
    }
    for (int i = idx; i < 1664*HH; i += gs){
        int n = i/HH, k = i - n*HH;
        float x = (n < G3) ? W_hh0[(size_t)n*HH + k] : W_out[(size_t)(n-G3)*HH + k];
        splitw(x, &wA_hi[i], &wA_lo[i]);
    }
    for (int i = idx; i < G3*DD; i += gs){
        int q = i/DD, k = i - q*DD;
        int gi = q/24, w = q%24, gate = w>>3, j = gi*8 + (w&7);
        splitw(W_ih0[(size_t)(gate*HH + j)*DD + k], &wB_hi[i], &wB_lo[i]);
    }
    for (int i = idx; i < 3072*HH; i += gs){
        int q = i/HH, k = i - q*HH;
        int gi = q/48, w = q%48, half = w/24, g3 = (w%24)>>3, jo = w&7;
        int j = gi*8 + jo;
        float x = (half == 0) ? W_ih1[(size_t)(g3*HH + j)*HH + k]
                              : W_hh1[(size_t)(g3*HH + j)*HH + k];
        splitw(x, &wC_hi[i], &wC_lo[i]);
    }
}

__device__ __forceinline__ u32 s2u(const void* p){
    u32 a; asm("{ .reg .u64 t; cvta.to.shared.u64 t, %1; cvt.u32.u64 %0, t; }" : "=r"(a) : "l"(p));
    return a;
}
__device__ __forceinline__ void cpasync16(u32 dst, const void* src){
    asm volatile("cp.async.cg.shared.global [%0], [%1], 16;" :: "r"(dst), "l"(src));
}
#define CP_COMMIT() asm volatile("cp.async.commit_group;" ::: "memory")
#define CP_WAIT0()  asm volatile("cp.async.wait_group 0;" ::: "memory")

__device__ __forceinline__ void mma_bf(float* d, u32 a0,u32 a1,u32 a2,u32 a3, u32 b0,u32 b1){
    asm volatile("mma.sync.aligned.m16n8k16.row.col.f32.bf16.bf16.f32 "
        "{%0,%1,%2,%3},{%4,%5,%6,%7},{%8,%9},{%0,%1,%2,%3};"
        : "+f"(d[0]),"+f"(d[1]),"+f"(d[2]),"+f"(d[3])
        : "r"(a0),"r"(a1),"r"(a2),"r"(a3),"r"(b0),"r"(b1));
}
__device__ __forceinline__ void ldsm4(u32* r, u32 a){
    asm volatile("ldmatrix.sync.aligned.m8n8.x4.shared.b16 {%0,%1,%2,%3}, [%4];"
        : "=r"(r[0]),"=r"(r[1]),"=r"(r[2]),"=r"(r[3]) : "r"(a));
}
__device__ __forceinline__ void ldsm2(u32* r, u32 a){
    asm volatile("ldmatrix.sync.aligned.m8n8.x2.shared.b16 {%0,%1}, [%2];"
        : "=r"(r[0]),"=r"(r[1]) : "r"(a));
}

__device__ __forceinline__ void grid_barrier(unsigned &target){
    __syncthreads();
    target += gridDim.x;
    if (threadIdx.x == 0){
        __threadfence();
        atomicAdd(&g_bar, 1u);
        int sp = 0;
        while (*((volatile unsigned*)&g_bar) < target)
            if (++sp > 256) __nanosleep(32);
    }
    __syncthreads();
}
__device__ __forceinline__ float sigf(float x){ return 1.f/(1.f+expf(-x)); }

// ---- smem: 2-buffer ring (A 64 rows hi/lo + W 48 rows hi/lo) + resident B weights
#define AH_OFF  0u
#define AL_OFF  9216u
#define WH_OFF  18432u
#define WL_OFF  25344u
#define BUF_SZ  32256u
#define RESB_HI 64512u
#define RESB_LO 71424u
#define SMEMSZ  78336

extern __shared__ __align__(16) char smc[];

template<int WROWS>
__device__ __forceinline__ void load_chunk(int buf, const bf* Ahi, const bf* Alo, int lda,
                                           const bf* W1, const bf* W2, int KW, int kc)
{
    const int tid = threadIdx.x;
    const u32 b = s2u(smc) + (u32)buf*BUF_SZ;
    int seg = tid;
    #pragma unroll
    for (int i = 0; i < 2; i++, seg += NTH){  // 512 segs = 64 rows x 8
        int r = seg >> 3, c = seg & 7;
        u32 d = b + r*144 + c*16;
        cpasync16(d + AH_OFF, Ahi + (size_t)r*lda + kc + c*8);
        cpasync16(d + AL_OFF, Alo + (size_t)r*lda + kc + c*8);
    }
    if (WROWS > 0){
        for (int s = tid; s < WROWS*8; s += NTH){
            int r = s >> 3, c = s & 7;
            u32 d = b + r*144 + c*16;
            cpasync16(d + WH_OFF, W1 + (size_t)r*KW + kc + c*8);
            cpasync16(d + WL_OFF, W2 + (size_t)r*KW + kc + c*8);
        }
    }
}

template<int NFR>
__device__ __forceinline__ void mma_chunk(u32 sAh, u32 sAl, u32 sWh, u32 sWl,
                                          int wm, int wn, float (*accH)[4], float (*accM)[4])
{
    const int lane = threadIdx.x & 31;
    const int lg = lane & 7, grp = lane >> 3;
    const u32 arow = (u32)(wm + lg + (grp & 1)*8) * 144 + ((grp >> 1) & 1)*16;
    const int l16 = lane & 15;
    const u32 brow0 = (u32)(l16 & 7) * 144 + (u32)(l16 >> 3) * 16;
    #pragma unroll
    for (int k16 = 0; k16 < 4; k16++){
        u32 ah[4], al[4];
        ldsm4(ah, sAh + arow + k16*32);
        ldsm4(al, sAl + arow + k16*32);
        #pragma unroll
        for (int nf = 0; nf < NFR; nf++){
            u32 boff = brow0 + (u32)(wn + 8*nf)*144 + k16*32;
            u32 bh[2], bl[2];
            ldsm2(bh, sWh + boff);
            ldsm2(bl, sWl + boff);
            mma_bf(accH[nf], ah[0],ah[1],ah[2],ah[3], bh[0],bh[1]);
            mma_bf(accM[nf], ah[0],ah[1],ah[2],ah[3], bl[0],bl[1]);
            mma_bf(accM[nf], al[0],al[1],al[2],al[3], bh[0],bh[1]);
        }
    }
}

// 2-buffer ring, depth-1 prefetch, one sync per chunk.
template<int NC, int WROWS, int NFR>
__device__ __forceinline__ void gemm_run(const bf* Ahi, const bf* Alo, int lda,
    const bf* W1, const bf* W2, int KW, int wm, int wn,
    float (*accH)[4], float (*accM)[4])
{
    #pragma unroll
    for (int n = 0; n < NFR; n++)
        #pragma unroll
        for (int q = 0; q < 4; q++){ accH[n][q] = 0.f; accM[n][q] = 0.f; }

    load_chunk<WROWS>(0, Ahi, Alo, lda, W1, W2, KW, 0);
    CP_COMMIT();
    const u32 sb = s2u(smc);
    for (int ch = 0; ch < NC; ch++){
        CP_WAIT0();
        __syncthreads();
        if (ch + 1 < NC){
            load_chunk<WROWS>((ch+1)&1, Ahi, Alo, lda, W1, W2, KW, (ch+1)*64);
            CP_COMMIT();
        }
        const u32 b = sb + (u32)(ch&1)*BUF_SZ;
        mma_chunk<NFR>(b+AH_OFF, b+AL_OFF, b+WH_OFF, b+WL_OFF, wm, wn, accH, accM);
    }
}

__global__ void __launch_bounds__(NTH, 2) brits_kernel(
    const float* __restrict__ X,     const float* __restrict__ Msk,
    const float* __restrict__ b_ih0, const float* __restrict__ b_hh0,
    const float* __restrict__ b_ih1, const float* __restrict__ b_hh1,
    const float* __restrict__ W_out, const float* __restrict__ b_out,
    float* __restrict__ out)
{
    const int tid = threadIdx.x, wid = tid >> 5, lane = tid & 31, bx = blockIdx.x;
    const int g = lane >> 2, t = lane & 3;
    const int half = wid & 1;             // n-half / K-half
    const int wm = (wid >> 1) * 16;       // m-frag base within 64-row tile
    float* xbuf = (float*)smc;            // aliases ring buf0 (dead at epilogue)

    float* pre_o = out;
    float* out_o = out + (size_t)BB*TT*DD;
    float* hf_o  = out + (size_t)2*BB*TT*DD;
    float* hid_o = hf_o + (size_t)BB*HH;

    unsigned target = 0;
    const int gs   = gridDim.x * blockDim.x;
    const int gtid = bx * blockDim.x + tid;
    const u32 sb = s2u(smc);

    for (int ts = 0; ts < TT; ts++){
        // ---- A: [gh0 | est] = h @ [W_hh0;W_out]^T. 208 tiles 64m x 32n, K=512
        for (int tile = bx; tile < 208; tile += gridDim.x){
            const int m0 = (tile / 52) * 64, n0 = (tile % 52) * 32;
            const int wn = half * 16;
            float accH[2][4], accM[2][4];
            gemm_run<8,32,2>(g_h_hi + (size_t)m0*HH, g_h_lo + (size_t)m0*HH, HH,
                             wA_hi + (size_t)n0*HH, wA_lo + (size_t)n0*HH, HH, wm, wn, accH, accM);
            #pragma unroll
            for (int nf = 0; nf < 2; nf++)
                #pragma unroll
                for (int rh = 0; rh < 2; rh++)
                    #pragma unroll
                    for (int d = 0; d < 2; d++){
                        int m = m0 + wm + g + 8*rh;
                        int n = n0 + wn + 8*nf + 2*t + d;
                        float v = accH[nf][rh*2+d] + accM[nf][rh*2+d];
                        if (n < G3) g_gh0[m*G3 + n] = v + b_hh0[n];
                        else {
                            int dd = n - G3;
                            float est = v + b_out[dd];
                            int io = (m*TT + ts)*DD + dd;
                            pre_o[io] = est;
                            float imp = est + Msk[io] * (X[io] - est);
                            bf hi = __float2bfloat16(imp);
                            g_imp_hi[m*DD + dd] = hi;
                            g_imp_lo[m*DD + dd] = __float2bfloat16(imp - __bfloat162float(hi));
                            if (ts > 0) out_o[io - DD] = imp;
                        }
                    }
        }
        grid_barrier(target);

        // ---- B: fused cell-0. 256 tiles 64m x 24n, K=128 split across halves. Resident W.
        for (int tile = bx; tile < 256; tile += gridDim.x){
            const int m0 = (tile / 64) * 64, jt = tile % 64, j0 = jt * 8;
            const int qB = jt * 24;
            // resident W load for this tile (small: 24 rows x 2 chunks hi/lo)
            for (int s = tid; s < 2*24*8; s += NTH){
                int ch = s / 192, r = (s >> 3) % 24, c = s & 7;
                *(uint4*)(smc + RESB_HI + (ch*24 + r)*144 + c*16) =
                    __ldg((const uint4*)(wB_hi + (size_t)(qB + r)*DD + ch*64 + c*8));
                *(uint4*)(smc + RESB_LO + (ch*24 + r)*144 + c*16) =
                    __ldg((const uint4*)(wB_lo + (size_t)(qB + r)*DD + ch*64 + c*8));
            }
            load_chunk<0>(0, g_imp_hi + (size_t)m0*DD, g_imp_lo + (size_t)m0*DD, DD,
                          (const bf*)0, (const bf*)0, DD, 0);
            load_chunk<0>(1, g_imp_hi + (size_t)m0*DD, g_imp_lo + (size_t)m0*DD, DD,
                          (const bf*)0, (const bf*)0, DD, 64);
            CP_COMMIT(); CP_WAIT0();
            __syncthreads();
            float accH[3][4], accM[3][4];
            #pragma unroll
            for (int n = 0; n < 3; n++)
                #pragma unroll
                for (int q = 0; q < 4; q++){ accH[n][q] = 0.f; accM[n][q] = 0.f; }
            const u32 b = sb + (u32)half*BUF_SZ;
            mma_chunk<3>(b+AH_OFF, b+AL_OFF,
                         sb + RESB_HI + (u32)half*24*144, sb + RESB_LO + (u32)half*24*144,
                         wm, 0, accH, accM);
            __syncthreads();
            if (half == 1)
                #pragma unroll
                for (int nf = 0; nf < 3; nf++)
                    #pragma unroll
                    for (int rh = 0; rh < 2; rh++)
                        #pragma unroll
                        for (int d = 0; d < 2; d++)
                            xbuf[(wm + g + 8*rh)*24 + nf*8 + 2*t + d] =
                                accH[nf][rh*2+d] + accM[nf][rh*2+d];
            __syncthreads();
            if (half == 0)
                #pragma unroll
                for (int rh = 0; rh < 2; rh++)
                    #pragma unroll
                    for (int d = 0; d < 2; d++){
                        int m = m0 + wm + g + 8*rh;
                        int j = j0 + 2*t + d;
                        int q = rh*2 + d;
                        int xb = (wm + g + 8*rh)*24 + 2*t + d;
                        float gr = accH[0][q]+accM[0][q] + xbuf[xb]    + b_ih0[j]      + __ldcg(&g_gh0[m*G3 + j]);
                        float gz = accH[1][q]+accM[1][q] + xbuf[xb+8]  + b_ih0[HH + j] + __ldcg(&g_gh0[m*G3 + HH + j]);
                        float gn = accH[2][q]+accM[2][q] + xbuf[xb+16] + b_ih0[2*HH + j];
                        float hn = __ldcg(&g_gh0[m*G3 + 2*HH + j]);
                        float r = sigf(gr), z = sigf(gz);
                        float nn = tanhf(gn + r * hn);
                        float hp = (1.f - z) * nn + z * __ldcg(&g_h[m*HH + j]);
                        g_hp[m*HH + j] = hp;
                        bf hi = __float2bfloat16(hp);
                        g_hp_hi[m*HH + j] = hi;
                        g_hp_lo[m*HH + j] = __float2bfloat16(hp - __bfloat162float(hi));
                    }
            __syncthreads();
        }
        grid_barrier(target);

        // ---- C: fused cell-1. 256 tiles 64m x 48n (half0 i-gates, half1 h-gates), K=512
        for (int tile = bx; tile < 256; tile += gridDim.x){
            const int m0 = (tile / 64) * 64, nt = tile % 64;
            const int q0 = nt * 48, j0 = nt * 8;
            const int wn = half * 24;
            float accH[3][4], accM[3][4];
            gemm_run<8,48,3>(g_hp_hi + (size_t)m0*HH, g_hp_lo + (size_t)m0*HH, HH,
                             wC_hi + (size_t)q0*HH, wC_lo + (size_t)q0*HH, HH, wm, wn, accH, accM);
            if (half == 1)
                #pragma unroll
                for (int nf = 0; nf < 3; nf++)
                    #pragma unroll
                    for (int rh = 0; rh < 2; rh++)
                        #pragma unroll
                        for (int d = 0; d < 2; d++)
                            xbuf[((wm + g + 8*rh)*8 + 2*t + d)*3 + nf] =
                                accH[nf][rh*2+d] + accM[nf][rh*2+d];
            __syncthreads();
            if (half == 0)
                #pragma unroll
                for (int rh = 0; rh < 2; rh++)
                    #pragma unroll
                    for (int d = 0; d < 2; d++){
                        int ml = wm + g + 8*rh, m = m0 + ml;
                        int jo = 2*t + d, j = j0 + jo;
                        int q = rh*2 + d;
                        const float* xb = &xbuf[(ml*8 + jo)*3];
                        float ir = accH[0][q]+accM[0][q], iz = accH[1][q]+accM[1][q], in_ = accH[2][q]+accM[2][q];
                        float hr = xb[0], hz = xb[1], hn = xb[2];
                        float r = sigf(ir + b_ih1[j] + hr + b_hh1[j]);
                        float z = sigf(iz + b_ih1[HH+j] + hz + b_hh1[HH+j]);
                        float nn = tanhf(in_ + b_ih1[2*HH+j] + r * (hn + b_hh1[2*HH+j]));
                        float hnew = (1.f - z) * nn + z * __ldcg(&g_hp[m*HH + j]);
                        g_h[m*HH + j] = hnew;
                        bf hi = __float2bfloat16(hnew);
                        g_h_hi[m*HH + j] = hi;
                        g_h_lo[m*HH + j] = __float2bfloat16(hnew - __bfloat162float(hi));
                        hid_o[((size_t)m*TT + ts)*HH + j] = hnew;
                    }
            __syncthreads();
        }
        grid_barrier(target);
    }

    // tail
    for (int idx = gtid; idx < BB*DD; idx += gs){
        int b = idx >> 7, d = idx & 127;
        const float4* hv = (const float4*)(g_h + (size_t)b*HH);
        const float4* wv = (const float4*)(W_out + (size_t)d*HH);
        float s = b_out[d];
        #pragma unroll 8
        for (int q = 0; q < HH/4; q++){
            float4 a = __ldcg(&hv[q]); float4 w = __ldg(&wv[q]);
            s += a.x*w.x + a.y*w.y + a.z*w.z + a.w*w.w;
        }
        out_o[((size_t)b*TT + (TT-1))*DD + d] = s;
    }
    for (int idx = gtid; idx < BB*HH; idx += gs)
        hf_o[idx] = __ldcg(&g_h[idx]);
}

extern "C" void kernel_launch(void* const* d_in, const int* in_sizes, int n_in,
                              void* d_out, int out_size) {
    const float* X     = (const float*)d_in[0];
    const float* Msk   = (const float*)d_in[1];
    const float* W_ih0 = (const float*)d_in[2];
    const float* W_hh0 = (const float*)d_in[3];
    const float* b_ih0 = (const float*)d_in[4];
    const float* b_hh0 = (const float*)d_in[5];
    const float* W_ih1 = (const float*)d_in[6];
    const float* W_hh1 = (const float*)d_in[7];
    const float* b_ih1 = (const float*)d_in[8];
    const float* b_hh1 = (const float*)d_in[9];
    const float* W_out = (const float*)d_in[10];
    const float* b_out = (const float*)d_in[11];

    static int grid = 0;
    if (grid == 0){
        cudaFuncSetAttribute(brits_kernel, cudaFuncAttributeMaxDynamicSharedMemorySize, SMEMSZ);
        int occ = 1;
        cudaOccupancyMaxActiveBlocksPerMultiprocessor(&occ, brits_kernel, NTH, SMEMSZ);
        if (occ < 1) occ = 1;
        if (occ > 2) occ = 2;
        grid = 148 * occ;
    }
    init_kernel<<<512, 256>>>(W_ih0, W_hh0, W_ih1, W_hh1, W_out);
    brits_kernel<<<grid, NTH, SMEMSZ>>>(X, Msk, b_ih0, b_hh0, b_ih1, b_hh1,
                                        W_out, b_out, (float*)d_out);
}